// round 6
// baseline (speedup 1.0000x reference)
#include <cuda_runtime.h>
#include <stdint.h>

// Problem constants (fixed by the dataset)
#define NN    100000
#define EE    3200000
#define INC   128
#define HIDC  128
#define OUTC  64

// ---------------------------------------------------------------------------
// Scratch (device globals: allocation-free per harness rules)
// ---------------------------------------------------------------------------
__device__ __align__(16) float g_dinv[NN];                 // rsqrt(degree)
__device__ __align__(16) float g_h1  [(size_t)NN * HIDC];  // x @ W1
__device__ __align__(16) float g_agg1[(size_t)NN * HIDC];  // P @ h1 (pre-bias/relu)
__device__ __align__(16) float g_h2  [(size_t)NN * OUTC];  // relu(agg1+b1) @ W2

// ---------------------------------------------------------------------------
// Fire-and-forget global reductions (sm_90+ vector red)
// ---------------------------------------------------------------------------
__device__ __forceinline__ void red_add_f32(float* p, float v) {
    asm volatile("red.global.add.f32 [%0], %1;" :: "l"(p), "f"(v) : "memory");
}
__device__ __forceinline__ void red_add_v4(float* p, float a, float b, float c, float d) {
    asm volatile("red.global.add.v4.f32 [%0], {%1,%2,%3,%4};"
                 :: "l"(p), "f"(a), "f"(b), "f"(c), "f"(d) : "memory");
}

// ---------------------------------------------------------------------------
// Degree / normalization  (edge_index is INT32: JAX x64 is disabled)
// ---------------------------------------------------------------------------
__global__ void k_deg_init() {
    int i = blockIdx.x * blockDim.x + threadIdx.x;
    if (i < NN) g_dinv[i] = 1.0f;   // self-loop contributes 1 to in-degree
}

__global__ void k_deg_accum(const int* __restrict__ ei) {
    int e = blockIdx.x * blockDim.x + threadIdx.x;
    if (e < EE) {
        int d = __ldg(&ei[EE + e]);   // dst row
        red_add_f32(&g_dinv[d], 1.0f);
    }
}

__global__ void k_dinv_finalize() {
    int i = blockIdx.x * blockDim.x + threadIdx.x;
    if (i < NN) {
        float deg = g_dinv[i];
        g_dinv[i] = (deg > 0.f) ? rsqrtf(deg) : 0.f;
    }
}

// ---------------------------------------------------------------------------
// GEMM1: h1 = x @ W1  [N,128] = [N,128]@[128,128]
// epilogue also seeds agg1 with the self-loop term dinv^2 * h1
// Block: 256 thr (16x16), tile 64 rows x 128 cols, K chunked by 32.
// ---------------------------------------------------------------------------
__global__ __launch_bounds__(256) void k_gemm1(const float* __restrict__ X,
                                               const float* __restrict__ W) {
    __shared__ float Xs[64 * 33];
    __shared__ float Ws[32 * 132];
    const int tid = threadIdx.x;
    const int tx = tid & 15, ty = tid >> 4;
    const int row0 = blockIdx.x * 64;

    float acc[4][8];
#pragma unroll
    for (int j = 0; j < 4; j++)
#pragma unroll
        for (int i = 0; i < 8; i++) acc[j][i] = 0.f;

    for (int kk = 0; kk < INC; kk += 32) {
        // X tile: 64 rows x 32 k  (coalesced 128B/warp)
#pragma unroll
        for (int j = 0; j < 8; j++) {
            int idx = tid + 256 * j;           // 0..2047
            int r = idx >> 5, k = idx & 31;
            int row = row0 + r;
            Xs[r * 33 + k] = (row < NN) ? X[(size_t)row * INC + kk + k] : 0.f;
        }
        // W chunk: 32 k x 128 cols (float4 coalesced)
#pragma unroll
        for (int j = 0; j < 4; j++) {
            int i4 = (tid + 256 * j) * 4;      // 0..4095
            int k = i4 >> 7, c = i4 & 127;
            float4 w = *(const float4*)&W[(size_t)(kk + k) * HIDC + c];
            *(float4*)&Ws[k * 132 + c] = w;
        }
        __syncthreads();

#pragma unroll
        for (int k = 0; k < 32; k++) {
            float4 w0 = *(const float4*)&Ws[k * 132 + tx * 4];
            float4 w1 = *(const float4*)&Ws[k * 132 + 64 + tx * 4];
#pragma unroll
            for (int j = 0; j < 4; j++) {
                float xv = Xs[(ty * 4 + j) * 33 + k];
                acc[j][0] += xv * w0.x; acc[j][1] += xv * w0.y;
                acc[j][2] += xv * w0.z; acc[j][3] += xv * w0.w;
                acc[j][4] += xv * w1.x; acc[j][5] += xv * w1.y;
                acc[j][6] += xv * w1.z; acc[j][7] += xv * w1.w;
            }
        }
        __syncthreads();
    }

#pragma unroll
    for (int j = 0; j < 4; j++) {
        int row = row0 + ty * 4 + j;
        if (row < NN) {
            float dv = g_dinv[row];
            float dd = dv * dv;
            float4 a0 = make_float4(acc[j][0], acc[j][1], acc[j][2], acc[j][3]);
            float4 a1 = make_float4(acc[j][4], acc[j][5], acc[j][6], acc[j][7]);
            *(float4*)&g_h1[(size_t)row * HIDC + tx * 4]      = a0;
            *(float4*)&g_h1[(size_t)row * HIDC + 64 + tx * 4] = a1;
            float4 s0 = make_float4(dd * a0.x, dd * a0.y, dd * a0.z, dd * a0.w);
            float4 s1 = make_float4(dd * a1.x, dd * a1.y, dd * a1.z, dd * a1.w);
            *(float4*)&g_agg1[(size_t)row * HIDC + tx * 4]      = s0;
            *(float4*)&g_agg1[(size_t)row * HIDC + 64 + tx * 4] = s1;
        }
    }
}

// ---------------------------------------------------------------------------
// Edge aggregation, layer 1: agg1[dst] += norm * h1[src]  (128 floats/edge)
// One warp per edge: each lane owns one float4 (512B coalesced both sides).
// ---------------------------------------------------------------------------
__global__ __launch_bounds__(256) void k_agg1(const int* __restrict__ ei) {
    int w = (blockIdx.x * 256 + threadIdx.x) >> 5;
    int lane = threadIdx.x & 31;
    if (w >= EE) return;
    int s = __ldg(&ei[w]);
    int d = __ldg(&ei[EE + w]);
    float nrm = __ldg(&g_dinv[s]) * __ldg(&g_dinv[d]);
    float4 v = *(const float4*)&g_h1[(size_t)s * HIDC + lane * 4];
    red_add_v4(&g_agg1[(size_t)d * HIDC + lane * 4],
               nrm * v.x, nrm * v.y, nrm * v.z, nrm * v.w);
}

// ---------------------------------------------------------------------------
// GEMM2: h2 = relu(agg1 + b1) @ W2   [N,64]
// epilogue seeds d_out with self-loop term + b2.
// Block 256 thr (16x16), tile 64 rows x 64 cols, K chunked by 32.
// ---------------------------------------------------------------------------
__global__ __launch_bounds__(256) void k_gemm2(const float* __restrict__ b1,
                                               const float* __restrict__ W2,
                                               const float* __restrict__ b2,
                                               float* __restrict__ out) {
    __shared__ float As[64 * 33];
    __shared__ float Ws[32 * 68];
    const int tid = threadIdx.x;
    const int tx = tid & 15, ty = tid >> 4;
    const int row0 = blockIdx.x * 64;

    float acc[4][4];
#pragma unroll
    for (int j = 0; j < 4; j++)
#pragma unroll
        for (int i = 0; i < 4; i++) acc[j][i] = 0.f;

    for (int kk = 0; kk < HIDC; kk += 32) {
        // A tile with fused bias + relu
#pragma unroll
        for (int j = 0; j < 8; j++) {
            int idx = tid + 256 * j;
            int r = idx >> 5, k = idx & 31;
            int row = row0 + r;
            float v = 0.f;
            if (row < NN) {
                v = g_agg1[(size_t)row * HIDC + kk + k] + b1[kk + k];
                v = fmaxf(v, 0.f);
            }
            As[r * 33 + k] = v;
        }
        // W2 chunk: 32 k x 64 cols
#pragma unroll
        for (int j = 0; j < 2; j++) {
            int i4 = (tid + 256 * j) * 4;      // 0..2047
            int k = i4 >> 6, c = i4 & 63;
            float4 w = *(const float4*)&W2[(size_t)(kk + k) * OUTC + c];
            *(float4*)&Ws[k * 68 + c] = w;
        }
        __syncthreads();

#pragma unroll
        for (int k = 0; k < 32; k++) {
            float4 w = *(const float4*)&Ws[k * 68 + tx * 4];
#pragma unroll
            for (int j = 0; j < 4; j++) {
                float xv = As[(ty * 4 + j) * 33 + k];
                acc[j][0] += xv * w.x; acc[j][1] += xv * w.y;
                acc[j][2] += xv * w.z; acc[j][3] += xv * w.w;
            }
        }
        __syncthreads();
    }

    float4 bb = *(const float4*)&b2[tx * 4];
#pragma unroll
    for (int j = 0; j < 4; j++) {
        int row = row0 + ty * 4 + j;
        if (row < NN) {
            float dv = g_dinv[row];
            float dd = dv * dv;
            float4 a = make_float4(acc[j][0], acc[j][1], acc[j][2], acc[j][3]);
            *(float4*)&g_h2[(size_t)row * OUTC + tx * 4] = a;
            float4 o = make_float4(dd * a.x + bb.x, dd * a.y + bb.y,
                                   dd * a.z + bb.z, dd * a.w + bb.w);
            *(float4*)&out[(size_t)row * OUTC + tx * 4] = o;
        }
    }
}

// ---------------------------------------------------------------------------
// Edge aggregation, layer 2: out[dst] += norm * h2[src]  (64 floats/edge)
// Half-warp per edge: 16 lanes x float4.
// ---------------------------------------------------------------------------
__global__ __launch_bounds__(256) void k_agg2(const int* __restrict__ ei,
                                              float* __restrict__ out) {
    int t = blockIdx.x * 256 + threadIdx.x;
    int e = t >> 4;
    int l = t & 15;
    if (e >= EE) return;
    int s = __ldg(&ei[e]);
    int d = __ldg(&ei[EE + e]);
    float nrm = __ldg(&g_dinv[s]) * __ldg(&g_dinv[d]);
    float4 v = *(const float4*)&g_h2[(size_t)s * OUTC + l * 4];
    red_add_v4(&out[(size_t)d * OUTC + l * 4],
               nrm * v.x, nrm * v.y, nrm * v.z, nrm * v.w);
}

// ---------------------------------------------------------------------------
// Launch
// ---------------------------------------------------------------------------
extern "C" void kernel_launch(void* const* d_in, const int* in_sizes, int n_in,
                              void* d_out, int out_size) {
    const float* x  = (const float*)d_in[0];
    const int*   ei = (const int*)d_in[1];     // int32! (JAX x64 disabled)
    const float* W1 = (const float*)d_in[2];
    const float* b1 = (const float*)d_in[3];
    const float* W2 = (const float*)d_in[4];
    const float* b2 = (const float*)d_in[5];
    float*       out = (float*)d_out;

    k_deg_init     <<<(NN + 255) / 256, 256>>>();
    k_deg_accum    <<<(EE + 255) / 256, 256>>>(ei);
    k_dinv_finalize<<<(NN + 255) / 256, 256>>>();

    k_gemm1<<<(NN + 63) / 64, 256>>>(x, W1);
    k_agg1 <<<(EE + 7)  / 8,  256>>>(ei);          // 1 warp / edge

    k_gemm2<<<(NN + 63) / 64, 256>>>(b1, W2, b2, out);
    k_agg2 <<<(EE + 15) / 16, 256>>>(ei, out);     // half-warp / edge
}

// round 7
// speedup vs baseline: 2.0456x; 2.0456x over previous
#include <cuda_runtime.h>
#include <stdint.h>

#define NN    100000
#define EE    3200000
#define INC   128
#define HIDC  128
#define OUTC  64
#define NBLK  ((NN + 1023) / 1024)     // 98 scan blocks

// ---------------------------------------------------------------------------
// Scratch (device globals: allocation-free per harness rules)
// ---------------------------------------------------------------------------
__device__ __align__(16) float g_dinv[NN];                  // rsqrt(deg+1)
__device__ __align__(16) float g_h1  [(size_t)NN * HIDC];   // dinv * (x @ W1)
__device__ __align__(16) float g_agg1[(size_t)NN * HIDC];   // layer-1 aggregate (pre-bias)
__device__ __align__(16) float g_h2  [(size_t)NN * OUTC];   // dinv * (relu(agg1+b1) @ W2)
__device__ int g_cnt[NN];          // in-degree (w/o self loop)
__device__ int g_rowptr[NN];       // CSR row start (exclusive scan of cnt)
__device__ int g_cursor[NN];       // scatter cursor
__device__ int g_blocksum[128];    // scan partials
__device__ int g_srcsorted[EE];    // src ids grouped by dst

// ---------------------------------------------------------------------------
// CSR build: histogram -> 2-level exclusive scan -> scatter
// ---------------------------------------------------------------------------
__global__ void k_zero_cnt() {
    int i = blockIdx.x * blockDim.x + threadIdx.x;
    if (i < NN) g_cnt[i] = 0;
}

__global__ void k_hist(const int* __restrict__ ei) {
    int e = blockIdx.x * blockDim.x + threadIdx.x;
    if (e < EE) atomicAdd(&g_cnt[__ldg(&ei[EE + e])], 1);   // no return use -> RED
}

__global__ __launch_bounds__(1024) void k_scan1() {
    __shared__ int sh[1024];
    int tid = threadIdx.x;
    int i = blockIdx.x * 1024 + tid;
    int v = (i < NN) ? g_cnt[i] : 0;
    sh[tid] = v;
    __syncthreads();
#pragma unroll
    for (int off = 1; off < 1024; off <<= 1) {
        int t = (tid >= off) ? sh[tid - off] : 0;
        __syncthreads();
        sh[tid] += t;
        __syncthreads();
    }
    if (i < NN) g_rowptr[i] = sh[tid];                    // inclusive, fixed later
    if (tid == 1023) g_blocksum[blockIdx.x] = sh[1023];
}

__global__ __launch_bounds__(128) void k_scan2() {
    __shared__ int sh[128];
    int tid = threadIdx.x;
    int v = (tid < NBLK) ? g_blocksum[tid] : 0;
    sh[tid] = v;
    __syncthreads();
#pragma unroll
    for (int off = 1; off < 128; off <<= 1) {
        int t = (tid >= off) ? sh[tid - off] : 0;
        __syncthreads();
        sh[tid] += t;
        __syncthreads();
    }
    if (tid < NBLK) g_blocksum[tid] = sh[tid] - v;        // exclusive block offsets
}

__global__ __launch_bounds__(1024) void k_scan3() {
    int i = blockIdx.x * 1024 + threadIdx.x;
    if (i < NN) {
        int cnt  = g_cnt[i];
        int excl = g_rowptr[i] - cnt + g_blocksum[blockIdx.x];
        g_rowptr[i] = excl;
        g_cursor[i] = excl;
        g_dinv[i]   = rsqrtf((float)(cnt + 1));           // +1 self loop
    }
}

__global__ void k_scatter(const int* __restrict__ ei) {
    int e = blockIdx.x * blockDim.x + threadIdx.x;
    if (e < EE) {
        int s = __ldg(&ei[e]);
        int d = __ldg(&ei[EE + e]);
        int pos = atomicAdd(&g_cursor[d], 1);
        g_srcsorted[pos] = s;
    }
}

// ---------------------------------------------------------------------------
// GEMM1: g_h1 = dinv .* (x @ W1)
// ---------------------------------------------------------------------------
__global__ __launch_bounds__(256) void k_gemm1(const float* __restrict__ X,
                                               const float* __restrict__ W) {
    __shared__ float Xs[64 * 33];
    __shared__ float Ws[32 * 132];
    const int tid = threadIdx.x;
    const int tx = tid & 15, ty = tid >> 4;
    const int row0 = blockIdx.x * 64;

    float acc[4][8];
#pragma unroll
    for (int j = 0; j < 4; j++)
#pragma unroll
        for (int i = 0; i < 8; i++) acc[j][i] = 0.f;

    for (int kk = 0; kk < INC; kk += 32) {
#pragma unroll
        for (int j = 0; j < 8; j++) {
            int idx = tid + 256 * j;
            int r = idx >> 5, k = idx & 31;
            int row = row0 + r;
            Xs[r * 33 + k] = (row < NN) ? X[(size_t)row * INC + kk + k] : 0.f;
        }
#pragma unroll
        for (int j = 0; j < 4; j++) {
            int i4 = (tid + 256 * j) * 4;
            int k = i4 >> 7, c = i4 & 127;
            float4 w = *(const float4*)&W[(size_t)(kk + k) * HIDC + c];
            *(float4*)&Ws[k * 132 + c] = w;
        }
        __syncthreads();

#pragma unroll
        for (int k = 0; k < 32; k++) {
            float4 w0 = *(const float4*)&Ws[k * 132 + tx * 4];
            float4 w1 = *(const float4*)&Ws[k * 132 + 64 + tx * 4];
#pragma unroll
            for (int j = 0; j < 4; j++) {
                float xv = Xs[(ty * 4 + j) * 33 + k];
                acc[j][0] += xv * w0.x; acc[j][1] += xv * w0.y;
                acc[j][2] += xv * w0.z; acc[j][3] += xv * w0.w;
                acc[j][4] += xv * w1.x; acc[j][5] += xv * w1.y;
                acc[j][6] += xv * w1.z; acc[j][7] += xv * w1.w;
            }
        }
        __syncthreads();
    }

#pragma unroll
    for (int j = 0; j < 4; j++) {
        int row = row0 + ty * 4 + j;
        if (row < NN) {
            float dv = g_dinv[row];
            float4 a0 = make_float4(dv * acc[j][0], dv * acc[j][1], dv * acc[j][2], dv * acc[j][3]);
            float4 a1 = make_float4(dv * acc[j][4], dv * acc[j][5], dv * acc[j][6], dv * acc[j][7]);
            *(float4*)&g_h1[(size_t)row * HIDC + tx * 4]      = a0;
            *(float4*)&g_h1[(size_t)row * HIDC + 64 + tx * 4] = a1;
        }
    }
}

// ---------------------------------------------------------------------------
// Layer-1 aggregation (CSR, gather-only): one warp per node, lane = float4.
// agg1[d] = dinv[d] * (h1s[d] + sum_{src in row(d)} h1s[src])
// ---------------------------------------------------------------------------
__global__ __launch_bounds__(256) void k_agg1_csr() {
    int node = (blockIdx.x * 256 + threadIdx.x) >> 5;
    int lane = threadIdx.x & 31;
    if (node >= NN) return;
    int beg = g_rowptr[node];
    int cnt = g_cnt[node];
    size_t co = (size_t)lane * 4;

    float4 acc = *(const float4*)&g_h1[(size_t)node * HIDC + co];   // self loop
    int i = 0;
    for (; i + 4 <= cnt; i += 4) {
        int s0 = __ldg(&g_srcsorted[beg + i]);
        int s1 = __ldg(&g_srcsorted[beg + i + 1]);
        int s2 = __ldg(&g_srcsorted[beg + i + 2]);
        int s3 = __ldg(&g_srcsorted[beg + i + 3]);
        float4 v0 = *(const float4*)&g_h1[(size_t)s0 * HIDC + co];
        float4 v1 = *(const float4*)&g_h1[(size_t)s1 * HIDC + co];
        float4 v2 = *(const float4*)&g_h1[(size_t)s2 * HIDC + co];
        float4 v3 = *(const float4*)&g_h1[(size_t)s3 * HIDC + co];
        acc.x += v0.x + v1.x + v2.x + v3.x;
        acc.y += v0.y + v1.y + v2.y + v3.y;
        acc.z += v0.z + v1.z + v2.z + v3.z;
        acc.w += v0.w + v1.w + v2.w + v3.w;
    }
    for (; i < cnt; i++) {
        int s = __ldg(&g_srcsorted[beg + i]);
        float4 v = *(const float4*)&g_h1[(size_t)s * HIDC + co];
        acc.x += v.x; acc.y += v.y; acc.z += v.z; acc.w += v.w;
    }
    float dv = g_dinv[node];
    *(float4*)&g_agg1[(size_t)node * HIDC + co] =
        make_float4(dv * acc.x, dv * acc.y, dv * acc.z, dv * acc.w);
}

// ---------------------------------------------------------------------------
// GEMM2: g_h2 = dinv .* (relu(agg1 + b1) @ W2)
// ---------------------------------------------------------------------------
__global__ __launch_bounds__(256) void k_gemm2(const float* __restrict__ b1,
                                               const float* __restrict__ W2) {
    __shared__ float As[64 * 33];
    __shared__ float Ws[32 * 68];
    const int tid = threadIdx.x;
    const int tx = tid & 15, ty = tid >> 4;
    const int row0 = blockIdx.x * 64;

    float acc[4][4];
#pragma unroll
    for (int j = 0; j < 4; j++)
#pragma unroll
        for (int i = 0; i < 4; i++) acc[j][i] = 0.f;

    for (int kk = 0; kk < HIDC; kk += 32) {
#pragma unroll
        for (int j = 0; j < 8; j++) {
            int idx = tid + 256 * j;
            int r = idx >> 5, k = idx & 31;
            int row = row0 + r;
            float v = 0.f;
            if (row < NN) {
                v = g_agg1[(size_t)row * HIDC + kk + k] + b1[kk + k];
                v = fmaxf(v, 0.f);
            }
            As[r * 33 + k] = v;
        }
#pragma unroll
        for (int j = 0; j < 2; j++) {
            int i4 = (tid + 256 * j) * 4;
            int k = i4 >> 6, c = i4 & 63;
            float4 w = *(const float4*)&W2[(size_t)(kk + k) * OUTC + c];
            *(float4*)&Ws[k * 68 + c] = w;
        }
        __syncthreads();

#pragma unroll
        for (int k = 0; k < 32; k++) {
            float4 w = *(const float4*)&Ws[k * 68 + tx * 4];
#pragma unroll
            for (int j = 0; j < 4; j++) {
                float xv = As[(ty * 4 + j) * 33 + k];
                acc[j][0] += xv * w.x; acc[j][1] += xv * w.y;
                acc[j][2] += xv * w.z; acc[j][3] += xv * w.w;
            }
        }
        __syncthreads();
    }

#pragma unroll
    for (int j = 0; j < 4; j++) {
        int row = row0 + ty * 4 + j;
        if (row < NN) {
            float dv = g_dinv[row];
            *(float4*)&g_h2[(size_t)row * OUTC + tx * 4] =
                make_float4(dv * acc[j][0], dv * acc[j][1], dv * acc[j][2], dv * acc[j][3]);
        }
    }
}

// ---------------------------------------------------------------------------
// Layer-2 aggregation (CSR): 16-lane group per node (64 ch), writes final out.
// out[d] = dinv[d] * (h2s[d] + sum h2s[src]) + b2
// ---------------------------------------------------------------------------
__global__ __launch_bounds__(256) void k_agg2_csr(const float* __restrict__ b2,
                                                  float* __restrict__ out) {
    int t = blockIdx.x * 256 + threadIdx.x;
    int node = t >> 4;
    int l = t & 15;
    if (node >= NN) return;
    int beg = g_rowptr[node];
    int cnt = g_cnt[node];
    size_t co = (size_t)l * 4;

    float4 acc = *(const float4*)&g_h2[(size_t)node * OUTC + co];   // self loop
    int i = 0;
    for (; i + 4 <= cnt; i += 4) {
        int s0 = __ldg(&g_srcsorted[beg + i]);
        int s1 = __ldg(&g_srcsorted[beg + i + 1]);
        int s2 = __ldg(&g_srcsorted[beg + i + 2]);
        int s3 = __ldg(&g_srcsorted[beg + i + 3]);
        float4 v0 = *(const float4*)&g_h2[(size_t)s0 * OUTC + co];
        float4 v1 = *(const float4*)&g_h2[(size_t)s1 * OUTC + co];
        float4 v2 = *(const float4*)&g_h2[(size_t)s2 * OUTC + co];
        float4 v3 = *(const float4*)&g_h2[(size_t)s3 * OUTC + co];
        acc.x += v0.x + v1.x + v2.x + v3.x;
        acc.y += v0.y + v1.y + v2.y + v3.y;
        acc.z += v0.z + v1.z + v2.z + v3.z;
        acc.w += v0.w + v1.w + v2.w + v3.w;
    }
    for (; i < cnt; i++) {
        int s = __ldg(&g_srcsorted[beg + i]);
        float4 v = *(const float4*)&g_h2[(size_t)s * OUTC + co];
        acc.x += v.x; acc.y += v.y; acc.z += v.z; acc.w += v.w;
    }
    float dv = g_dinv[node];
    float4 bb = *(const float4*)&b2[co];
    *(float4*)&out[(size_t)node * OUTC + co] =
        make_float4(dv * acc.x + bb.x, dv * acc.y + bb.y,
                    dv * acc.z + bb.z, dv * acc.w + bb.w);
}

// ---------------------------------------------------------------------------
// Launch
// ---------------------------------------------------------------------------
extern "C" void kernel_launch(void* const* d_in, const int* in_sizes, int n_in,
                              void* d_out, int out_size) {
    const float* x  = (const float*)d_in[0];
    const int*   ei = (const int*)d_in[1];     // int32 (JAX x64 disabled)
    const float* W1 = (const float*)d_in[2];
    const float* b1 = (const float*)d_in[3];
    const float* W2 = (const float*)d_in[4];
    const float* b2 = (const float*)d_in[5];
    float*       out = (float*)d_out;

    k_zero_cnt<<<(NN + 255) / 256, 256>>>();
    k_hist    <<<(EE + 255) / 256, 256>>>(ei);
    k_scan1   <<<NBLK, 1024>>>();
    k_scan2   <<<1, 128>>>();
    k_scan3   <<<NBLK, 1024>>>();
    k_scatter <<<(EE + 255) / 256, 256>>>(ei);

    k_gemm1   <<<(NN + 63) / 64, 256>>>(x, W1);
    k_agg1_csr<<<(NN * 32 + 255) / 256, 256>>>();

    k_gemm2   <<<(NN + 63) / 64, 256>>>(b1, W2);
    k_agg2_csr<<<(NN * 16 + 255) / 256, 256>>>(b2, out);
}